// round 12
// baseline (speedup 1.0000x reference)
#include <cuda_runtime.h>
#include <cuda_bf16.h>

#define NSP 8192
#define NR  2097152
#define NCTA 296
#define RSLICE 8          // rows per reduce CTA: 296 = 37 * 8

__device__ float g_partial[NCTA * NSP];   // 9.7 MB static scratch, overwritten each call

__device__ __forceinline__ float ex2_approx(float x) {
    float y;
    asm("ex2.approx.ftz.f32 %0, %1;" : "=f"(y) : "f"(x));
    return y;
}

__device__ __forceinline__ void red_shared_add(float* p, float v) {
    asm volatile("red.shared.add.f32 [%0], %1;"
                 :: "l"(__cvta_generic_to_shared(p)), "f"(v) : "memory");
}

struct Rxn {
    float a, b, g;
    int   t;
    int2  sp;
    int4  rw;
};

__global__ __launch_bounds__(512, 2)
void rates_scatter_kernel(
    const float* __restrict__ abund,
    const float* __restrict__ Tptr,
    const float* __restrict__ crptr,
    const float* __restrict__ fuvptr,
    const float* __restrict__ alpha,
    const float* __restrict__ beta,
    const float* __restrict__ gamma,
    const int*   __restrict__ rtype,
    const int2*  __restrict__ rspec,
    const int4*  __restrict__ rows4,
    float* __restrict__ out)
{
    extern __shared__ float smem[];
    float* acc = smem;          // [NSP] per-CTA accumulator
    float* sab = smem + NSP;    // [NSP] staged abundances

    for (int i = threadIdx.x; i < NSP; i += blockDim.x) {
        acc[i] = 0.0f;
        sab[i] = abund[i];
    }
    // Zero poisoned output; reduce runs strictly after this kernel (stream order).
    if (blockIdx.x == 0)
        for (int i = threadIdx.x; i < NSP; i += blockDim.x) out[i] = 0.0f;
    __syncthreads();

    const float T   = *Tptr;
    const float cr  = *crptr;
    const float fuv = *fuvptr;
    const float L2E = 1.4426950408889634f;           // log2(e)
    const float c1  = __log2f(T * (1.0f / 300.0f));  // log2(T/300)
    const float c2  = -L2E / T;                      // exp(-g/T) = exp2(g*c2)

    const int stride = gridDim.x * blockDim.x;
    int r = blockIdx.x * blockDim.x + threadIdx.x;

    Rxn cur;
    if (r < NR) {
        cur.a = alpha[r]; cur.b = beta[r]; cur.g = gamma[r];
        cur.t = rtype[r]; cur.sp = rspec[r]; cur.rw = rows4[r];
    }

    while (r < NR) {
        const int rn = r + stride;

        // Prefetch next iteration's streaming loads.
        Rxn nxt;
        if (rn < NR) {
            nxt.a = alpha[rn]; nxt.b = beta[rn]; nxt.g = gamma[rn];
            nxt.t = rtype[rn]; nxt.sp = rspec[rn]; nxt.rw = rows4[rn];
        }

        {
            const float e  = (cur.t == 0) ? fmaf(cur.b, c1, cur.g * c2)
                                          : (-cur.g * L2E);
            const float ex = ex2_approx(e);
            float k;
            if (cur.t == 1)      k = cur.a * cr;
            else if (cur.t == 2) k = cur.a * fuv * ex;
            else                 k = cur.a * ex;

            k *= sab[cur.sp.x] * sab[cur.sp.y];

            red_shared_add(&acc[cur.rw.x], -k);
            red_shared_add(&acc[cur.rw.y], -k);
            red_shared_add(&acc[cur.rw.z],  k);
            red_shared_add(&acc[cur.rw.w],  k);
        }

        cur = nxt;
        r = rn;
    }

    __syncthreads();
    // Plain coalesced STG flush (proven ~6 us cheaper than REDG flush).
    float* mine = g_partial + (size_t)blockIdx.x * NSP;
    for (int i = threadIdx.x; i < NSP; i += blockDim.x)
        mine[i] = acc[i];
}

// Parallel fold over L2-resident partials.
// Grid (8, 37), 256 threads. CTA (bx, by): species chunk [bx*1024, +1024) as
// float4 per thread; rows [by*8, by*8+8) with 8-deep MLP. 37 REDG per address.
__global__ __launch_bounds__(256, 8)
void reduce_kernel(float* __restrict__ out) {
    const int q  = blockIdx.x * blockDim.x + threadIdx.x;   // float4 index
    const int c0 = blockIdx.y * RSLICE;
    const float4* p = (const float4*)(g_partial + (size_t)c0 * NSP) + q;
    const int step = NSP / 4;

    float4 v[RSLICE];
    #pragma unroll
    for (int c = 0; c < RSLICE; c++)      // 8 independent LDG.128
        v[c] = p[(size_t)c * step];

    float sx = 0.f, sy = 0.f, sz = 0.f, sw = 0.f;
    #pragma unroll
    for (int c = 0; c < RSLICE; c++) {
        sx += v[c].x; sy += v[c].y; sz += v[c].z; sw += v[c].w;
    }

    float* o = out + 4 * q;
    atomicAdd(o + 0, sx);    // no-return REDG, 37 per address
    atomicAdd(o + 1, sy);
    atomicAdd(o + 2, sz);
    atomicAdd(o + 3, sw);
}

extern "C" void kernel_launch(void* const* d_in, const int* in_sizes, int n_in,
                              void* d_out, int out_size) {
    const float* abund  = (const float*)d_in[0];
    const float* T      = (const float*)d_in[1];
    const float* crr    = (const float*)d_in[2];
    const float* fuvr   = (const float*)d_in[3];
    float* out = (float*)d_out;

    const int smem_bytes = 2 * NSP * sizeof(float);  // 64 KB
    cudaFuncSetAttribute(rates_scatter_kernel,
                         cudaFuncAttributeMaxDynamicSharedMemorySize, smem_bytes);

    rates_scatter_kernel<<<NCTA, 512, smem_bytes>>>(
        abund, T, crr, fuvr,
        (const float*)d_in[4], (const float*)d_in[5], (const float*)d_in[6],
        (const int*)d_in[7], (const int2*)d_in[8], (const int4*)d_in[9],
        out);

    reduce_kernel<<<dim3(NSP / 1024, 37), 256>>>(out);
}